// round 1
// baseline (speedup 1.0000x reference)
#include <cuda_runtime.h>
#include <cuda_bf16.h>
#include <cstdint>

// NeRF emission-absorption raymarcher.
// Inputs (metadata order):
//   d_in[0]: rays_densities (B,R,N,1) float32   -> B*R*N elems
//   d_in[1]: rays_features  (B,R,N,F) float32   -> B*R*N*F elems
//   d_in[2]: lengths        (B,R,N)   float32   -> B*R*N elems
// Output: (B,R,F+1) float32, F=3 -> 4 floats per ray.
//
// One warp per ray. Lane i owns samples [4i, 4i+4). All loads are float4,
// consecutive lanes -> consecutive 16B -> fully coalesced.
// absorption[i] = exclusive prefix product of a_k = (1+EPS-d_k):
//   per-lane local products + warp inclusive shuffle-scan + shift-by-one.

#define EPS 1e-10f

__global__ __launch_bounds__(256, 8)
void ea_raymarch_kernel(const float* __restrict__ dens,
                        const float* __restrict__ feat,
                        const float* __restrict__ lens,
                        float* __restrict__ out,
                        int n_rays)
{
    const int warps_per_block = blockDim.x >> 5;
    const int ray = blockIdx.x * warps_per_block + (threadIdx.x >> 5);
    if (ray >= n_rays) return;
    const int lane = threadIdx.x & 31;

    // N = 128, F = 3 (fixed shapes for this problem)
    const long long base_n  = (long long)ray * 128;      // densities / lengths base (floats)
    const long long base_f  = (long long)ray * 384;      // features base (floats)

    // ---- loads: one float4 of densities, one of lengths, three of features ----
    const float4 d4 = __ldg((const float4*)(dens + base_n) + lane);
    const float4 l4 = __ldg((const float4*)(lens + base_n) + lane);
    const float4* fptr = (const float4*)(feat + base_f) + 3 * lane;
    const float4 f4a = __ldg(fptr + 0);   // f[4i+0].xyz, f[4i+1].x
    const float4 f4b = __ldg(fptr + 1);   // f[4i+1].yz,  f[4i+2].xy
    const float4 f4c = __ldg(fptr + 2);   // f[4i+2].z,   f[4i+3].xyz

    // a_k = 1 + EPS - d_k
    const float a0 = 1.0f + EPS - d4.x;
    const float a1 = 1.0f + EPS - d4.y;
    const float a2 = 1.0f + EPS - d4.z;
    const float a3 = 1.0f + EPS - d4.w;

    // local total product for the scan
    float t = (a0 * a1) * (a2 * a3);

    // warp inclusive product scan of t
    float incl = t;
    #pragma unroll
    for (int off = 1; off < 32; off <<= 1) {
        float v = __shfl_up_sync(0xffffffffu, incl, off);
        if (lane >= off) incl *= v;
    }
    // exclusive: shift by one lane
    float excl = __shfl_up_sync(0xffffffffu, incl, 1);
    if (lane == 0) excl = 1.0f;

    // per-sample absorptions and weights
    const float ab0 = excl;
    const float ab1 = ab0 * a0;
    const float ab2 = ab1 * a1;
    const float ab3 = ab2 * a2;

    const float w0 = d4.x * ab0;
    const float w1 = d4.y * ab1;
    const float w2 = d4.z * ab2;
    const float w3 = d4.w * ab3;

    // feature channel unpack per sample:
    // s0: (f4a.x, f4a.y, f4a.z)   s1: (f4a.w, f4b.x, f4b.y)
    // s2: (f4b.z, f4b.w, f4c.x)   s3: (f4c.y, f4c.z, f4c.w)
    float r = w0 * f4a.x + w1 * f4a.w + w2 * f4b.z + w3 * f4c.y;
    float g = w0 * f4a.y + w1 * f4b.x + w2 * f4b.w + w3 * f4c.z;
    float b = w0 * f4a.z + w1 * f4b.y + w2 * f4c.x + w3 * f4c.w;

    float depth = w0 * l4.x + w1 * l4.y + w2 * l4.z + w3 * l4.w;
    float alpha = (w0 + w1) + (w2 + w3);

    // warp reductions (sum) for the 5 accumulators
    #pragma unroll
    for (int off = 16; off > 0; off >>= 1) {
        r     += __shfl_down_sync(0xffffffffu, r,     off);
        g     += __shfl_down_sync(0xffffffffu, g,     off);
        b     += __shfl_down_sync(0xffffffffu, b,     off);
        depth += __shfl_down_sync(0xffffffffu, depth, off);
        alpha += __shfl_down_sync(0xffffffffu, alpha, off);
    }

    // last length along the ray = lane 31's l4.w
    const float last_len = __shfl_sync(0xffffffffu, l4.w, 31);

    if (lane == 0) {
        const float one_m_alpha = 1.0f - alpha;
        float4 o;
        o.x = r + one_m_alpha;                 // WHITE_BG
        o.y = g + one_m_alpha;
        o.z = b + one_m_alpha;
        o.w = depth + one_m_alpha * last_len;  // background depth fill
        ((float4*)out)[ray] = o;
    }
}

extern "C" void kernel_launch(void* const* d_in, const int* in_sizes, int n_in,
                              void* d_out, int out_size)
{
    const float* dens = (const float*)d_in[0];
    const float* feat = (const float*)d_in[1];
    const float* lens = (const float*)d_in[2];
    float* out = (float*)d_out;

    // out_size = n_rays * (F+1) = n_rays * 4
    const int n_rays = out_size / 4;          // 131072 for this problem

    const int threads = 256;                  // 8 warps/block
    const int warps_per_block = threads / 32;
    const int blocks = (n_rays + warps_per_block - 1) / warps_per_block;

    ea_raymarch_kernel<<<blocks, threads>>>(dens, feat, lens, out, n_rays);
}

// round 2
// speedup vs baseline: 1.0316x; 1.0316x over previous
#include <cuda_runtime.h>
#include <cuda_bf16.h>
#include <cstdint>

// NeRF emission-absorption raymarcher.
// Inputs (metadata order):
//   d_in[0]: rays_densities (B,R,N,1) float32   -> B*R*N elems
//   d_in[1]: rays_features  (B,R,N,F) float32   -> B*R*N*F elems
//   d_in[2]: lengths        (B,R,N)   float32   -> B*R*N elems
// Output: (B,R,F+1) float32, F=3 -> 4 floats per ray.
//
// One warp per ray. Lane i owns samples [4i, 4i+4). All loads are float4,
// consecutive lanes -> consecutive 16B -> fully coalesced.
// R2: all loads use streaming (evict-first) policy — 335 MB streams through
// a 126 MB L2 with zero reuse; evict-first frees L2 ways on the fill path.

#define EPS 1e-10f

__global__ __launch_bounds__(256, 8)
void ea_raymarch_kernel(const float* __restrict__ dens,
                        const float* __restrict__ feat,
                        const float* __restrict__ lens,
                        float* __restrict__ out,
                        int n_rays)
{
    const int warps_per_block = blockDim.x >> 5;
    const int ray = blockIdx.x * warps_per_block + (threadIdx.x >> 5);
    if (ray >= n_rays) return;
    const int lane = threadIdx.x & 31;

    // N = 128, F = 3 (fixed shapes for this problem)
    const long long base_n  = (long long)ray * 128;      // densities / lengths base (floats)
    const long long base_f  = (long long)ray * 384;      // features base (floats)

    // ---- loads: streaming (evict-first). one float4 of densities, one of
    // lengths, three of features ----
    const float4 d4 = __ldcs((const float4*)(dens + base_n) + lane);
    const float4 l4 = __ldcs((const float4*)(lens + base_n) + lane);
    const float4* fptr = (const float4*)(feat + base_f) + 3 * lane;
    const float4 f4a = __ldcs(fptr + 0);   // f[4i+0].xyz, f[4i+1].x
    const float4 f4b = __ldcs(fptr + 1);   // f[4i+1].yz,  f[4i+2].xy
    const float4 f4c = __ldcs(fptr + 2);   // f[4i+2].z,   f[4i+3].xyz

    // a_k = 1 + EPS - d_k
    const float a0 = 1.0f + EPS - d4.x;
    const float a1 = 1.0f + EPS - d4.y;
    const float a2 = 1.0f + EPS - d4.z;
    const float a3 = 1.0f + EPS - d4.w;

    // local total product for the scan
    float t = (a0 * a1) * (a2 * a3);

    // warp inclusive product scan of t
    float incl = t;
    #pragma unroll
    for (int off = 1; off < 32; off <<= 1) {
        float v = __shfl_up_sync(0xffffffffu, incl, off);
        if (lane >= off) incl *= v;
    }
    // exclusive: shift by one lane
    float excl = __shfl_up_sync(0xffffffffu, incl, 1);
    if (lane == 0) excl = 1.0f;

    // per-sample absorptions and weights
    const float ab0 = excl;
    const float ab1 = ab0 * a0;
    const float ab2 = ab1 * a1;
    const float ab3 = ab2 * a2;

    const float w0 = d4.x * ab0;
    const float w1 = d4.y * ab1;
    const float w2 = d4.z * ab2;
    const float w3 = d4.w * ab3;

    // feature channel unpack per sample:
    // s0: (f4a.x, f4a.y, f4a.z)   s1: (f4a.w, f4b.x, f4b.y)
    // s2: (f4b.z, f4b.w, f4c.x)   s3: (f4c.y, f4c.z, f4c.w)
    float r = w0 * f4a.x + w1 * f4a.w + w2 * f4b.z + w3 * f4c.y;
    float g = w0 * f4a.y + w1 * f4b.x + w2 * f4b.w + w3 * f4c.z;
    float b = w0 * f4a.z + w1 * f4b.y + w2 * f4c.x + w3 * f4c.w;

    float depth = w0 * l4.x + w1 * l4.y + w2 * l4.z + w3 * l4.w;
    float alpha = (w0 + w1) + (w2 + w3);

    // warp reductions (sum) for the 5 accumulators
    #pragma unroll
    for (int off = 16; off > 0; off >>= 1) {
        r     += __shfl_down_sync(0xffffffffu, r,     off);
        g     += __shfl_down_sync(0xffffffffu, g,     off);
        b     += __shfl_down_sync(0xffffffffu, b,     off);
        depth += __shfl_down_sync(0xffffffffu, depth, off);
        alpha += __shfl_down_sync(0xffffffffu, alpha, off);
    }

    // last length along the ray = lane 31's l4.w
    const float last_len = __shfl_sync(0xffffffffu, l4.w, 31);

    if (lane == 0) {
        const float one_m_alpha = 1.0f - alpha;
        float4 o;
        o.x = r + one_m_alpha;                 // WHITE_BG
        o.y = g + one_m_alpha;
        o.z = b + one_m_alpha;
        o.w = depth + one_m_alpha * last_len;  // background depth fill
        __stcs((float4*)out + ray, o);
    }
}

extern "C" void kernel_launch(void* const* d_in, const int* in_sizes, int n_in,
                              void* d_out, int out_size)
{
    const float* dens = (const float*)d_in[0];
    const float* feat = (const float*)d_in[1];
    const float* lens = (const float*)d_in[2];
    float* out = (float*)d_out;

    // out_size = n_rays * (F+1) = n_rays * 4
    const int n_rays = out_size / 4;          // 131072 for this problem

    const int threads = 256;                  // 8 warps/block
    const int warps_per_block = threads / 32;
    const int blocks = (n_rays + warps_per_block - 1) / warps_per_block;

    ea_raymarch_kernel<<<blocks, threads>>>(dens, feat, lens, out, n_rays);
}